// round 12
// baseline (speedup 1.0000x reference)
#include <cuda_runtime.h>
#include <cuda_bf16.h>
#include <cuda_fp16.h>
#include <cstdint>

// Problem dims
#define BB   32
#define TT   512
#define II   512
#define HH   1024
#define OO   512
#define MM   (BB*TT)

#define RNN_BLOCKS 64
#define MEGA_GRID  148
#define WORKERS    (MEGA_GRID - RNN_BLOCKS)   // 84

// ---------------- scratch (static device globals) ---------------------------
__device__ float g_pre[MM * HH];
__device__ float g_logits[MM * OO];
__device__ float g_zfallback[MM * HH];

__device__ __half g_xh[MM * II],    g_xl[MM * II];
__device__ __half g_wihh[HH * II],  g_wihl[HH * II];
__device__ __half g_wouth[OO * HH], g_woutl[OO * HH];
__device__ __half g_zh16[MM * HH],  g_zl16[MM * HH];

// sync state (zeroed by init kernel each launch)
__device__ unsigned g_flags[RNN_BLOCKS * 2 * 32];   // per (block, mw-half), spread
__device__ unsigned g_pre_done[4 * 32];             // per t-chunk of 128, spread
__device__ unsigned g_split_done[32];

// ---------------- helpers ----------------------------------------------------
__device__ __forceinline__ void mma16816h(float& d0, float& d1, float& d2, float& d3,
                                          uint32_t a0, uint32_t a1, uint32_t a2, uint32_t a3,
                                          uint32_t b0, uint32_t b1)
{
    asm volatile(
        "mma.sync.aligned.m16n8k16.row.col.f32.f16.f16.f32 "
        "{%0,%1,%2,%3},{%4,%5,%6,%7},{%8,%9},{%0,%1,%2,%3};"
        : "+f"(d0), "+f"(d1), "+f"(d2), "+f"(d3)
        : "r"(a0), "r"(a1), "r"(a2), "r"(a3), "r"(b0), "r"(b1));
}

__device__ __forceinline__ void ldsm4(uint32_t& r0, uint32_t& r1, uint32_t& r2, uint32_t& r3,
                                      uint32_t addr)
{
    asm volatile("ldmatrix.sync.aligned.m8n8.x4.shared.b16 {%0,%1,%2,%3}, [%4];"
                 : "=r"(r0), "=r"(r1), "=r"(r2), "=r"(r3) : "r"(addr));
}

__device__ __forceinline__ uint32_t lds32(uint32_t a) {
    uint32_t v;
    asm volatile("ld.shared.b32 %0, [%1];" : "=r"(v) : "r"(a));
    return v;
}

__device__ __forceinline__ void cpa16(uint32_t s, const void* g) {
    asm volatile("cp.async.cg.shared.global [%0], [%1], 16;" :: "r"(s), "l"(g));
}

__device__ __forceinline__ uint32_t pack_h2(float x, float y) {
    __half2 t = __floats2half2_rn(x, y);
    return *reinterpret_cast<uint32_t*>(&t);
}

__device__ __forceinline__ void flag_store(unsigned* p, unsigned v) {
    asm volatile("st.release.gpu.u32 [%0], %1;" :: "l"(p), "r"(v));
}
__device__ __forceinline__ void flag_wait(const unsigned* p, unsigned target) {
    unsigned v;
    do {
        asm volatile("ld.acquire.gpu.u32 %0, [%1];" : "=r"(v) : "l"(p));
    } while ((int)(v - target) < 0);
}

__device__ __forceinline__ void nbar_sync(int id, int cnt) {
    asm volatile("bar.sync %0, %1;" :: "r"(id), "r"(cnt) : "memory");
}
__device__ __forceinline__ void nbar_arrive(int id, int cnt) {
    asm volatile("bar.arrive %0, %1;" :: "r"(id), "r"(cnt) : "memory");
}

// ---------------- init: zero all sync state (replay-safe) --------------------
__global__ void init_sync()
{
    int i = blockIdx.x * 256 + threadIdx.x;
    if (i < RNN_BLOCKS * 2 * 32) g_flags[i] = 0;
    if (i < 4 * 32)              g_pre_done[i] = 0;
    if (i < 32)                  g_split_done[i] = 0;
}

// ---------------- GEMM tile (fp16-pair, 3-term), device function -------------
// C[128,128] tile at (m0,n0): A rows m0..m0+127 (K), B rows n0..+127 (K).
#define GT_BYTES  (128 * 80)
#define GBUF      (4 * GT_BYTES)
#define GSMEM     (2 * GBUF)      // 81920

__device__ void gemm_tile(char* dsm, int tid, int m0, int n0, int K, int N,
                          const __half* __restrict__ Ah, const __half* __restrict__ Al,
                          const __half* __restrict__ Bh, const __half* __restrict__ Bl,
                          const float* __restrict__ bias1, const float* __restrict__ bias2,
                          float* __restrict__ C)
{
    const uint32_t sb = (uint32_t)__cvta_generic_to_shared(dsm);
    const int wid  = tid >> 5;
    const int lane = tid & 31;
    const int grp  = lane >> 2;
    const int tig  = lane & 3;
    const int wm   = wid & 1;
    const int wn   = wid >> 1;

    float acc[4][4][4];
    #pragma unroll
    for (int i = 0; i < 4; i++)
        #pragma unroll
        for (int j = 0; j < 4; j++)
            #pragma unroll
            for (int q = 0; q < 4; q++) acc[i][j][q] = 0.f;

    const int lrow = tid >> 2;
    const int lc16 = tid & 3;

    const int KT = K >> 5;
    // prologue load kt=0 into buf 0
    for (int kt = 0; kt <= 0; kt++) {
        #pragma unroll
        for (int r = 0; r < 2; r++) {
            int row = lrow + r * 64;
            uint32_t so = row * 80 + lc16 * 16;
            size_t goA = (size_t)(m0 + row) * K + lc16 * 8;
            size_t goB = (size_t)(n0 + row) * K + lc16 * 8;
            cpa16(sb + so,                Ah + goA);
            cpa16(sb + so + GT_BYTES,     Al + goA);
            cpa16(sb + so + 2 * GT_BYTES, Bh + goB);
            cpa16(sb + so + 3 * GT_BYTES, Bl + goB);
        }
        asm volatile("cp.async.commit_group;" ::: "memory");
    }

    for (int kt = 0; kt < KT; kt++) {
        if (kt + 1 < KT) {
            int buf = (kt + 1) & 1;
            #pragma unroll
            for (int r = 0; r < 2; r++) {
                int row = lrow + r * 64;
                uint32_t so = (uint32_t)buf * GBUF + row * 80 + lc16 * 16;
                size_t goA = (size_t)(m0 + row) * K + (kt + 1) * 32 + lc16 * 8;
                size_t goB = (size_t)(n0 + row) * K + (kt + 1) * 32 + lc16 * 8;
                cpa16(sb + so,                Ah + goA);
                cpa16(sb + so + GT_BYTES,     Al + goA);
                cpa16(sb + so + 2 * GT_BYTES, Bh + goB);
                cpa16(sb + so + 3 * GT_BYTES, Bl + goB);
            }
            asm volatile("cp.async.commit_group;" ::: "memory");
            asm volatile("cp.async.wait_group 1;" ::: "memory");
        } else {
            asm volatile("cp.async.wait_group 0;" ::: "memory");
        }
        __syncthreads();

        const uint32_t bufo = (uint32_t)(kt & 1) * GBUF;
        #pragma unroll
        for (int h16 = 0; h16 < 2; h16++) {
            uint32_t ah[4][4], al[4][4];
            #pragma unroll
            for (int mi = 0; mi < 4; mi++) {
                int row = wm * 64 + mi * 16 + grp;
                uint32_t base = sb + bufo + row * 80 + h16 * 32 + tig * 4;
                ah[mi][0] = lds32(base);
                ah[mi][1] = lds32(base + 8 * 80);
                ah[mi][2] = lds32(base + 16);
                ah[mi][3] = lds32(base + 8 * 80 + 16);
                al[mi][0] = lds32(base + GT_BYTES);
                al[mi][1] = lds32(base + GT_BYTES + 8 * 80);
                al[mi][2] = lds32(base + GT_BYTES + 16);
                al[mi][3] = lds32(base + GT_BYTES + 8 * 80 + 16);
            }
            uint32_t bh[4][2], bl[4][2];
            #pragma unroll
            for (int ni = 0; ni < 4; ni++) {
                int row = wn * 32 + ni * 8 + grp;
                uint32_t base = sb + bufo + 2 * GT_BYTES + row * 80 + h16 * 32 + tig * 4;
                bh[ni][0] = lds32(base);
                bh[ni][1] = lds32(base + 16);
                bl[ni][0] = lds32(base + GT_BYTES);
                bl[ni][1] = lds32(base + GT_BYTES + 16);
            }
            #pragma unroll
            for (int mi = 0; mi < 4; mi++)
                #pragma unroll
                for (int ni = 0; ni < 4; ni++) {
                    float* a = acc[mi][ni];
                    mma16816h(a[0], a[1], a[2], a[3],
                              ah[mi][0], ah[mi][1], ah[mi][2], ah[mi][3],
                              bh[ni][0], bh[ni][1]);
                    mma16816h(a[0], a[1], a[2], a[3],
                              ah[mi][0], ah[mi][1], ah[mi][2], ah[mi][3],
                              bl[ni][0], bl[ni][1]);
                    mma16816h(a[0], a[1], a[2], a[3],
                              al[mi][0], al[mi][1], al[mi][2], al[mi][3],
                              bh[ni][0], bh[ni][1]);
                }
        }
        __syncthreads();
    }

    #pragma unroll
    for (int ni = 0; ni < 4; ni++) {
        int gc = n0 + wn * 32 + ni * 8 + tig * 2;
        float bs0 = 0.f, bs1 = 0.f;
        if (bias1) { bs0 += bias1[gc]; bs1 += bias1[gc + 1]; }
        if (bias2) { bs0 += bias2[gc]; bs1 += bias2[gc + 1]; }
        #pragma unroll
        for (int mi = 0; mi < 4; mi++) {
            int gr = m0 + wm * 64 + mi * 16 + grp;
            float* a = acc[mi][ni];
            *(float2*)&C[(size_t)gr * N + gc] = make_float2(a[0] + bs0, a[1] + bs1);
            *(float2*)&C[(size_t)(gr + 8) * N + gc] = make_float2(a[2] + bs0, a[3] + bs1);
        }
    }
}

// ---------------- fp32 -> fp16 hi/lo split (grid-stride) ----------------------
__device__ void split_range(const float* __restrict__ src,
                            __half* __restrict__ hi, __half* __restrict__ lo,
                            int n, int start, int stride)
{
    for (int i = start; i < n; i += stride) {
        float x = src[i];
        __half h = __float2half_rn(x);
        hi[i] = h;
        lo[i] = __float2half_rn(x - __half2float(h));
    }
}

// ---------------- recurrence constants ---------------------------------------
#define WBUF   8448
#define SM_PS  (8 * WBUF)              // 67584
#define PSROW  18
#define PS_KW  (16 * PSROW)
#define PS_HALF (4 * PS_KW)
#define MEGA_SMEM (SM_PS + 2 * 2 * PS_HALF * 4)   // 86016  (>= GSMEM)

// ---------------- recurrence role (blocks 0..63) ------------------------------
__device__ void rnn_role(char* dsm,
                         const float* __restrict__ pre,
                         const float* __restrict__ W_hh,
                         const float* __restrict__ h0g,
                         float* __restrict__ z_out)
{
    const uint32_t sb = (uint32_t)__cvta_generic_to_shared(dsm);
    const int tid  = threadIdx.x;
    const int wid  = tid >> 5;
    const int lane = tid & 31;
    const int grp  = lane >> 2;
    const int tig  = lane & 3;
    const int jc   = blockIdx.x;
    const int kw   = wid & 3;
    const int mw   = wid >> 2;

    // ---- preload W fragments (fp16) into registers ----
    uint32_t w0[2][16], w1[2][16];
    #pragma unroll
    for (int nt = 0; nt < 2; nt++) {
        const int jrow = jc * 16 + nt * 8 + grp;
        const float* Wr = W_hh + (size_t)jrow * HH + kw * 256;
        #pragma unroll
        for (int ki = 0; ki < 16; ki++) {
            int k0 = ki * 16 + tig * 2;
            w0[nt][ki] = pack_h2(Wr[k0],     Wr[k0 + 1]);
            w1[nt][ki] = pack_h2(Wr[k0 + 8], Wr[k0 + 9]);
        }
    }

    const uint32_t wb = sb + (uint32_t)wid * WBUF;
    char* wbp = dsm + wid * WBUF;
    const uint32_t lrow = (lane & 7) + ((lane >> 3) & 1) * 8;
    const uint32_t aoff = lrow * 528 + ((uint32_t)lane >> 4) * 16;

    const int pflag = ((kw * 16 + (lane & 15)) * 2 + mw) * 32;

    const int ltid = tid & 127;
    const int lb   = ltid >> 3;
    const int pbB  = mw * 16 + lb;
    const int pbJ  = (ltid & 7) * 2;

    float* const psum = (float*)(dsm + SM_PS);
    const int barA = 1 + mw;
    const int barB = 3 + mw;

    for (int t = 0; t < TT; t++) {
        // ---- pre-chunk gate (4x per run, per-warp) ----
        if ((t & 127) == 0) {
            if (lane == 0) {
                const unsigned* pd = &g_pre_done[(t >> 7) * 32];
                unsigned v;
                do {
                    asm volatile("ld.acquire.gpu.u32 %0, [%1];" : "=r"(v) : "l"(pd));
                } while (v < 256u);
            }
            __syncwarp();
        }

        // prefetch pre (phase-B input)
        float2 pre2 = *(const float2*)&pre[((size_t)pbB * TT + t) * HH + jc * 16 + pbJ];

        // ---- dataflow wait: 16 producer half-flags (1/lane) ----
        if (t > 0)
            flag_wait(&g_flags[pflag], (unsigned)t);
        __syncwarp();

        // ---- stage own 16x256 fp16 slice ----
        if (t == 0) {
            #pragma unroll
            for (int i = 0; i < 16; i++) {
                int chunk = i * 32 + lane;
                int row   = chunk >> 5;
                int c     = chunk & 31;
                size_t gi = (size_t)(mw * 16 + row) * HH + kw * 256 + c * 8;
                float4 f0 = *(const float4*)(h0g + gi);
                float4 f1 = *(const float4*)(h0g + gi + 4);
                uint4 v;
                v.x = pack_h2(f0.x, f0.y);
                v.y = pack_h2(f0.z, f0.w);
                v.z = pack_h2(f1.x, f1.y);
                v.w = pack_h2(f1.z, f1.w);
                *(uint4*)(wbp + row * 528 + c * 16) = v;
            }
            __syncwarp();
        } else {
            size_t off0 = ((size_t)(mw * 16) * TT + (t - 1)) * HH + kw * 256;
            #pragma unroll
            for (int i = 0; i < 16; i++) {
                int chunk = i * 32 + lane;
                int row   = chunk >> 5;
                int c     = chunk & 31;
                cpa16(wb + row * 528 + c * 16,
                      g_zh16 + off0 + (size_t)row * ((size_t)TT * HH) + c * 8);
            }
            asm volatile("cp.async.commit_group;" ::: "memory");
            asm volatile("cp.async.wait_group 0;" ::: "memory");
            __syncwarp();
        }

        // ---- mma over own k=256 ----
        float a1[2][4] = {{0,0,0,0},{0,0,0,0}};
        #pragma unroll
        for (int ki = 0; ki < 16; ki++) {
            uint32_t h0r, h1r, h2r, h3r;
            ldsm4(h0r, h1r, h2r, h3r, wb + aoff + ki * 32);
            #pragma unroll
            for (int nt = 0; nt < 2; nt++) {
                mma16816h(a1[nt][0], a1[nt][1], a1[nt][2], a1[nt][3],
                          h0r, h1r, h2r, h3r, w0[nt][ki], w1[nt][ki]);
            }
        }

        // ---- per-warp k-partials to SMEM (parity double-buffered) ----
        {
            float* pb = psum + ((t & 1) * 2 + mw) * PS_HALF + kw * PS_KW;
            #pragma unroll
            for (int nt = 0; nt < 2; nt++) {
                int jj = nt * 8 + tig * 2;
                float* p = pb + grp * PSROW + jj;
                *(float2*)p               = make_float2(a1[nt][0], a1[nt][1]);
                *(float2*)(p + 8 * PSROW) = make_float2(a1[nt][2], a1[nt][3]);
            }
        }
        nbar_sync(barA, 128);

        // ---- phase B: reduce 4 kw, tanh, publish z fp32 + fp16 pair ----
        {
            const float* pb = psum + ((t & 1) * 2 + mw) * PS_HALF;
            float s0 = pre2.x, s1 = pre2.y;
            #pragma unroll
            for (int kk = 0; kk < 4; kk++) {
                float2 p = *(float2*)&pb[kk * PS_KW + lb * PSROW + pbJ];
                s0 += p.x; s1 += p.y;
            }
            float h0v = tanhf(s0);
            float h1v = tanhf(s1);
            size_t zidx = ((size_t)pbB * TT + t) * HH + jc * 16 + pbJ;
            __half q0 = __float2half_rn(h0v);
            __half q1 = __float2half_rn(h1v);
            __half2 qh; qh.x = q0; qh.y = q1;
            *(uint32_t*)&g_zh16[zidx] = *(uint32_t*)&qh;
            *(uint32_t*)&g_zl16[zidx] = pack_h2(h0v - __half2float(q0),
                                                h1v - __half2float(q1));
            *(float2*)&z_out[zidx]    = make_float2(h0v, h1v);
        }

        if (kw == 0) {
            nbar_sync(barB, 128);
            if (lane == 0)
                flag_store(&g_flags[(blockIdx.x * 2 + mw) * 32], (unsigned)t + 1u);
        } else {
            nbar_arrive(barB, 128);
        }
    }
}

// ---------------- worker role (blocks 64..147) --------------------------------
__device__ void worker_role(char* dsm,
                            const float* __restrict__ x,
                            const float* __restrict__ W_ih,
                            const float* __restrict__ W_out,
                            const float* __restrict__ b_ih,
                            const float* __restrict__ b_hh,
                            const float* __restrict__ b_out)
{
    const int tid = threadIdx.x;
    const int w   = blockIdx.x - RNN_BLOCKS;    // 0..83
    const int start  = w * 256 + tid;
    const int stride = WORKERS * 256;

    // ---- Phase S: fp16-pair splits ----
    split_range(x,     g_xh,    g_xl,    MM * II, start, stride);
    split_range(W_ih,  g_wihh,  g_wihl,  HH * II, start, stride);
    split_range(W_out, g_wouth, g_woutl, OO * HH, start, stride);
    __syncthreads();
    if (tid == 0) {
        __threadfence();
        atomicAdd(&g_split_done[0], 1u);
    }
    {
        const unsigned* sd = &g_split_done[0];
        unsigned v;
        do {
            asm volatile("ld.acquire.gpu.u32 %0, [%1];" : "=r"(v) : "l"(sd));
        } while (v < (unsigned)WORKERS);
    }
    __syncthreads();

    // ---- Phase P: pre-GEMM tiles in t-chunk order ----
    for (int g = w; g < 1024; g += WORKERS) {
        int c   = g >> 8;
        int rem = g & 255;
        int b   = rem >> 3;
        int jt  = rem & 7;
        int m0  = b * TT + c * 128;
        int n0  = jt * 128;
        gemm_tile(dsm, tid, m0, n0, II, HH,
                  g_xh, g_xl, g_wihh, g_wihl, b_ih, b_hh, g_pre);
        __syncthreads();
        if (tid == 0) {
            __threadfence();
            atomicAdd(&g_pre_done[c * 32], 1u);
        }
        __syncthreads();
    }

    // ---- Phase O: out-GEMM tiles gated on z progress ----
    int gated_c = -1;
    for (int g = w; g < 512; g += WORKERS) {
        int c = g >> 7;
        if (c != gated_c) {
            if (tid < 128)
                flag_wait(&g_flags[tid * 32], (unsigned)(c * 128 + 128));
            __syncthreads();
            gated_c = c;
        }
        int rem = g & 127;
        int b   = rem >> 2;
        int jo  = rem & 3;
        int m0  = b * TT + c * 128;
        int n0  = jo * 128;
        gemm_tile(dsm, tid, m0, n0, HH, OO,
                  g_zh16, g_zl16, g_wouth, g_woutl, b_out, nullptr, g_logits);
        __syncthreads();
    }
}

// ---------------- mega kernel -------------------------------------------------
__global__ __launch_bounds__(256, 1)
void mega(const float* __restrict__ x,
          const float* __restrict__ h0,
          const float* __restrict__ W_ih,
          const float* __restrict__ W_hh,
          const float* __restrict__ b_ih,
          const float* __restrict__ b_hh,
          const float* __restrict__ W_out,
          const float* __restrict__ b_out,
          float* __restrict__ z_out)
{
    extern __shared__ __align__(16) char dsm[];
    if (blockIdx.x < RNN_BLOCKS)
        rnn_role(dsm, g_pre, W_hh, h0, z_out);
    else
        worker_role(dsm, x, W_ih, W_out, b_ih, b_hh, b_out);
}

// ---------------- row softmax over 512 cols ---------------------------------
__global__ __launch_bounds__(256)
void softmax512(const float* __restrict__ logits, float* __restrict__ out)
{
    const int row = blockIdx.x;
    const int tid = threadIdx.x;
    const float* in = logits + (size_t)row * OO;
    float a = in[tid], b = in[tid + 256];

    float m = fmaxf(a, b);
    #pragma unroll
    for (int o = 16; o > 0; o >>= 1)
        m = fmaxf(m, __shfl_xor_sync(0xffffffffu, m, o));
    __shared__ float redm[8];
    __shared__ float reds[8];
    if ((tid & 31) == 0) redm[tid >> 5] = m;
    __syncthreads();
    float mm = redm[0];
    #pragma unroll
    for (int i = 1; i < 8; i++) mm = fmaxf(mm, redm[i]);

    float e0 = expf(a - mm), e1 = expf(b - mm);
    float s = e0 + e1;
    #pragma unroll
    for (int o = 16; o > 0; o >>= 1)
        s += __shfl_xor_sync(0xffffffffu, s, o);
    if ((tid & 31) == 0) reds[tid >> 5] = s;
    __syncthreads();
    float ss = 0.f;
    #pragma unroll
    for (int i = 0; i < 8; i++) ss += reds[i];
    float inv = 1.0f / ss;

    float* op = out + (size_t)row * OO;
    op[tid]       = e0 * inv;
    op[tid + 256] = e1 * inv;
}

// ---------------- launch -----------------------------------------------------
extern "C" void kernel_launch(void* const* d_in, const int* in_sizes, int n_in,
                              void* d_out, int out_size)
{
    const float* x     = (const float*)d_in[0];
    const float* h0    = (const float*)d_in[1];
    const float* W_ih  = (const float*)d_in[2];
    const float* W_hh  = (const float*)d_in[3];
    const float* b_ih  = (const float*)d_in[4];
    const float* b_hh  = (const float*)d_in[5];
    const float* W_out = (const float*)d_in[6];
    const float* b_out = (const float*)d_in[7];
    float* out = (float*)d_out;

    float *logits, *zfb;
    cudaGetSymbolAddress((void**)&logits, g_logits);
    cudaGetSymbolAddress((void**)&zfb,    g_zfallback);

    cudaFuncSetAttribute(mega, cudaFuncAttributeMaxDynamicSharedMemorySize, MEGA_SMEM);

    float* z = (out_size >= (int)((size_t)MM * (OO + HH)))
                 ? out + (size_t)MM * OO : zfb;

    // 1) zero sync state (in-stream, before mega)
    init_sync<<<16, 256>>>();

    // 2) fused persistent kernel: splits + pre-GEMM + recurrence + out-GEMM
    mega<<<MEGA_GRID, 256, MEGA_SMEM>>>(x, h0, W_ih, W_hh, b_ih, b_hh, W_out, b_out, z);

    // 3) softmax rows -> out
    softmax512<<<MM, 256>>>(logits, out);
}

// round 13
// speedup vs baseline: 1.0260x; 1.0260x over previous
#include <cuda_runtime.h>
#include <cuda_bf16.h>
#include <cuda_fp16.h>
#include <cstdint>

// Problem dims
#define BB   32
#define TT   512
#define II   512
#define HH   1024
#define OO   512
#define MM   (BB*TT)

#define RNN_BLOCKS 64

// ---------------- scratch (static device globals) ---------------------------
__device__ float g_pre[MM * HH];
__device__ float g_logits[MM * OO];
__device__ float g_zfallback[MM * HH];

__device__ __half g_xh[MM * II],    g_xl[MM * II];
__device__ __half g_wihh[HH * II],  g_wihl[HH * II];
__device__ __half g_wouth[OO * HH], g_woutl[OO * HH];
__device__ __half g_zh16[MM * HH],  g_zl16[MM * HH];
__device__ __half g_h0h16[BB * HH];

// per-(block, mw-half) spread flags (128B apart)
__device__ unsigned g_flags[RNN_BLOCKS * 2 * 32];

// ---------------- helpers ----------------------------------------------------
__device__ __forceinline__ void mma16816h(float& d0, float& d1, float& d2, float& d3,
                                          uint32_t a0, uint32_t a1, uint32_t a2, uint32_t a3,
                                          uint32_t b0, uint32_t b1)
{
    asm volatile(
        "mma.sync.aligned.m16n8k16.row.col.f32.f16.f16.f32 "
        "{%0,%1,%2,%3},{%4,%5,%6,%7},{%8,%9},{%0,%1,%2,%3};"
        : "+f"(d0), "+f"(d1), "+f"(d2), "+f"(d3)
        : "r"(a0), "r"(a1), "r"(a2), "r"(a3), "r"(b0), "r"(b1));
}

__device__ __forceinline__ void ldsm4(uint32_t& r0, uint32_t& r1, uint32_t& r2, uint32_t& r3,
                                      uint32_t addr)
{
    asm volatile("ldmatrix.sync.aligned.m8n8.x4.shared.b16 {%0,%1,%2,%3}, [%4];"
                 : "=r"(r0), "=r"(r1), "=r"(r2), "=r"(r3) : "r"(addr));
}

__device__ __forceinline__ uint32_t lds32(uint32_t a) {
    uint32_t v;
    asm volatile("ld.shared.b32 %0, [%1];" : "=r"(v) : "r"(a));
    return v;
}

__device__ __forceinline__ void cpa16(uint32_t s, const void* g) {
    asm volatile("cp.async.cg.shared.global [%0], [%1], 16;" :: "r"(s), "l"(g));
}

__device__ __forceinline__ uint32_t pack_h2(float x, float y) {
    __half2 t = __floats2half2_rn(x, y);
    return *reinterpret_cast<uint32_t*>(&t);
}

__device__ __forceinline__ void flag_store(unsigned* p, unsigned v) {
    asm volatile("st.release.gpu.u32 [%0], %1;" :: "l"(p), "r"(v));
}
__device__ __forceinline__ void flag_wait(const unsigned* p, unsigned target) {
    unsigned v;
    do {
        asm volatile("ld.acquire.gpu.u32 %0, [%1];" : "=r"(v) : "l"(p));
    } while ((int)(v - target) < 0);
}

__device__ __forceinline__ void nbar_sync(int id, int cnt) {
    asm volatile("bar.sync %0, %1;" :: "r"(id), "r"(cnt) : "memory");
}
__device__ __forceinline__ void nbar_arrive(int id, int cnt) {
    asm volatile("bar.arrive %0, %1;" :: "r"(id), "r"(cnt) : "memory");
}

// ---------------- persistent Elman recurrence (fp16 state, dataflow) ---------
// 64 blocks x 256 threads, 1/SM. Block jc owns j in [jc*16, jc*16+16).
// 8 warps: kw=wid&3 (k chunk of 256), mw=wid>>2 (b half of 16).
// Per step: poll 16 producer half-flags (1/lane), stage private 16x256 fp16
// slice, 32 HMMA, half-scope psum reduce, phase B publishes z fp32 + fp16
// hi/lo pair. kw=0 syncs+publishes the half-flag; kw=1..3 arrive and fly.
#define WBUF   8448                    // per-warp fp16 slice
#define SM_PS  (8 * WBUF)              // 67584
#define PSROW  18
#define PS_KW  (16 * PSROW)
#define PS_HALF (4 * PS_KW)
#define RNN_SMEM (SM_PS + 2 * 2 * PS_HALF * 4)

__global__ __launch_bounds__(256, 1)
void rnn_persistent(const float* __restrict__ pre,
                    const float* __restrict__ W_hh,
                    float* __restrict__ z_out)
{
    extern __shared__ __align__(16) char dsm[];
    const uint32_t sb = (uint32_t)__cvta_generic_to_shared(dsm);

    const int tid  = threadIdx.x;
    const int wid  = tid >> 5;
    const int lane = tid & 31;
    const int grp  = lane >> 2;       // 0..7
    const int tig  = lane & 3;        // 0..3
    const int jc   = blockIdx.x;      // 0..63
    const int kw   = wid & 3;         // k chunk of 256
    const int mw   = wid >> 2;        // b half

    // replay-safe base (all flags equal at launch start)
    const unsigned base = g_flags[blockIdx.x * 64];

    // ---- preload W fragments (fp16) into registers, whole run ----
    uint32_t w0[2][16], w1[2][16];
    #pragma unroll
    for (int nt = 0; nt < 2; nt++) {
        const int jrow = jc * 16 + nt * 8 + grp;
        const float* Wr = W_hh + (size_t)jrow * HH + kw * 256;
        #pragma unroll
        for (int ki = 0; ki < 16; ki++) {
            int k0 = ki * 16 + tig * 2;
            w0[nt][ki] = pack_h2(Wr[k0],     Wr[k0 + 1]);
            w1[nt][ki] = pack_h2(Wr[k0 + 8], Wr[k0 + 9]);
        }
    }

    // warp-private staging buffer
    const uint32_t wb = sb + (uint32_t)wid * WBUF;
    const uint32_t lrow = (lane & 7) + ((lane >> 3) & 1) * 8;
    const uint32_t aoff = lrow * 528 + ((uint32_t)lane >> 4) * 16;

    // producer half-flag this lane polls: 16 producers cover k in [kw*256,+256)
    const int pflag = ((kw * 16 + (lane & 15)) * 2 + mw) * 32;

    // phase-B mapping within the 128-thread half
    const int ltid = tid & 127;
    const int lb   = ltid >> 3;               // local b 0..15
    const int pbB  = mw * 16 + lb;            // global b
    const int pbJ  = (ltid & 7) * 2;          // j pair within chunk

    float* const psum = (float*)(dsm + SM_PS);   // [parity][mw][kw][16][PSROW]

    const int barA = 1 + mw;   // psum-ready
    const int barB = 3 + mw;   // z-done

    for (int t = 0; t < TT; t++) {
        // prefetch pre (phase-B input, independent of h)
        float2 pre2 = *(const float2*)&pre[((size_t)pbB * TT + t) * HH + jc * 16 + pbJ];

        // ---- dataflow wait: this warp's 16 producer half-flags ----
        if (t > 0)
            flag_wait(&g_flags[pflag], base + (unsigned)t);
        __syncwarp();

        // ---- stage own 16-row x 256-k fp16 slice ----
        {
            const __half* sh;
            size_t rstride, off0;
            if (t == 0) {
                sh = g_h0h16;
                rstride = HH;
                off0 = (size_t)(mw * 16) * HH + kw * 256;
            } else {
                sh = g_zh16;
                rstride = (size_t)TT * HH;
                off0 = ((size_t)(mw * 16) * TT + (t - 1)) * HH + kw * 256;
            }
            #pragma unroll
            for (int i = 0; i < 16; i++) {
                int chunk = i * 32 + lane;
                int row   = chunk >> 5;
                int c     = chunk & 31;
                cpa16(wb + row * 528 + c * 16, sh + off0 + (size_t)row * rstride + c * 8);
            }
            asm volatile("cp.async.commit_group;" ::: "memory");
            asm volatile("cp.async.wait_group 0;" ::: "memory");
            __syncwarp();
        }

        // ---- mma over own k=256 (single fp16 term) ----
        float a1[2][4] = {{0,0,0,0},{0,0,0,0}};
        #pragma unroll
        for (int ki = 0; ki < 16; ki++) {
            uint32_t h0r, h1r, h2r, h3r;
            ldsm4(h0r, h1r, h2r, h3r, wb + aoff + ki * 32);
            #pragma unroll
            for (int nt = 0; nt < 2; nt++) {
                mma16816h(a1[nt][0], a1[nt][1], a1[nt][2], a1[nt][3],
                          h0r, h1r, h2r, h3r, w0[nt][ki], w1[nt][ki]);
            }
        }

        // ---- per-warp k-partials to SMEM (parity double-buffered) ----
        {
            float* pb = psum + ((t & 1) * 2 + mw) * PS_HALF + kw * PS_KW;
            #pragma unroll
            for (int nt = 0; nt < 2; nt++) {
                int jj = nt * 8 + tig * 2;
                float* p = pb + grp * PSROW + jj;
                *(float2*)p               = make_float2(a1[nt][0], a1[nt][1]);
                *(float2*)(p + 8 * PSROW) = make_float2(a1[nt][2], a1[nt][3]);
            }
        }
        nbar_sync(barA, 128);   // psum ready within this half

        // ---- phase B (2 elements/thread): reduce 4 kw, tanh, publish ----
        {
            const float* pb = psum + ((t & 1) * 2 + mw) * PS_HALF;
            float s0 = pre2.x, s1 = pre2.y;
            #pragma unroll
            for (int kk = 0; kk < 4; kk++) {
                float2 p = *(float2*)&pb[kk * PS_KW + lb * PSROW + pbJ];
                s0 += p.x; s1 += p.y;
            }
            float h0v = tanhf(s0);
            float h1v = tanhf(s1);
            size_t zidx = ((size_t)pbB * TT + t) * HH + jc * 16 + pbJ;
            __half q0 = __float2half_rn(h0v);
            __half q1 = __float2half_rn(h1v);
            __half2 qh; qh.x = q0; qh.y = q1;
            *(uint32_t*)&g_zh16[zidx] = *(uint32_t*)&qh;
            *(uint32_t*)&g_zl16[zidx] = pack_h2(h0v - __half2float(q0),
                                                h1v - __half2float(q1));
            *(float2*)&z_out[zidx]    = make_float2(h0v, h1v);
        }

        // ---- z-done: kw=0 warp syncs + publishes; others arrive & fly ----
        if (kw == 0) {
            nbar_sync(barB, 128);
            if (lane == 0)
                flag_store(&g_flags[(blockIdx.x * 2 + mw) * 32], base + (unsigned)t + 1u);
        } else {
            nbar_arrive(barB, 128);
        }
    }
}

// ---------------- fused prep: fp16-pair splits of x, W_ih, W_out; h0 conv ----
#define N_X   (MM * II)
#define N_WI  (HH * II)
#define N_WO  (OO * HH)
#define N_H0  (BB * HH)
#define N_PREP (N_X + N_WI + N_WO + N_H0)

__global__ __launch_bounds__(256)
void prep_all(const float* __restrict__ x, const float* __restrict__ W_ih,
              const float* __restrict__ W_out, const float* __restrict__ h0)
{
    int stride = gridDim.x * 256;
    for (int i = blockIdx.x * 256 + threadIdx.x; i < N_PREP; i += stride) {
        const float* src;
        __half *hi, *lo;
        int idx = i;
        if (idx < N_X)                    { src = x;     hi = g_xh;    lo = g_xl; }
        else if ((idx -= N_X) < N_WI)     { src = W_ih;  hi = g_wihh;  lo = g_wihl; }
        else if ((idx -= N_WI) < N_WO)    { src = W_out; hi = g_wouth; lo = g_woutl; }
        else { idx -= N_WO;
            g_h0h16[idx] = __float2half_rn(h0[idx]);
            continue;
        }
        float v = src[idx];
        __half h = __float2half_rn(v);
        hi[idx] = h;
        lo[idx] = __float2half_rn(v - __half2float(h));
    }
}

// ---------------- mma.sync fp16-pair 3-term GEMM -----------------------------
#define GT_BYTES  (128 * 80)
#define GBUF      (4 * GT_BYTES)
#define GSMEM     (2 * GBUF)

__global__ __launch_bounds__(256)
void hgemm(int M, int N, int K,
           const __half* __restrict__ Ah, const __half* __restrict__ Al,
           const __half* __restrict__ Bh, const __half* __restrict__ Bl,
           const float* __restrict__ bias1, const float* __restrict__ bias2,
           float* __restrict__ C)
{
    extern __shared__ __align__(16) char dsm[];
    const uint32_t sb = (uint32_t)__cvta_generic_to_shared(dsm);

    const int tid  = threadIdx.x;
    const int wid  = tid >> 5;
    const int lane = tid & 31;
    const int grp  = lane >> 2;
    const int tig  = lane & 3;
    const int wm   = wid & 1;
    const int wn   = wid >> 1;
    const int m0   = blockIdx.x * 128;
    const int n0   = blockIdx.y * 128;

    float acc[4][4][4];
    #pragma unroll
    for (int i = 0; i < 4; i++)
        #pragma unroll
        for (int j = 0; j < 4; j++)
            #pragma unroll
            for (int q = 0; q < 4; q++) acc[i][j][q] = 0.f;

    const int lrow = tid >> 2;
    const int lc16 = tid & 3;

    auto issue = [&](int kt, int buf) {
        #pragma unroll
        for (int r = 0; r < 2; r++) {
            int row = lrow + r * 64;
            uint32_t so = (uint32_t)buf * GBUF + row * 80 + lc16 * 16;
            size_t goA = (size_t)(m0 + row) * K + kt * 32 + lc16 * 8;
            size_t goB = (size_t)(n0 + row) * K + kt * 32 + lc16 * 8;
            cpa16(sb + so,                Ah + goA);
            cpa16(sb + so + GT_BYTES,     Al + goA);
            cpa16(sb + so + 2 * GT_BYTES, Bh + goB);
            cpa16(sb + so + 3 * GT_BYTES, Bl + goB);
        }
        asm volatile("cp.async.commit_group;" ::: "memory");
    };

    const int KT = K >> 5;
    issue(0, 0);

    for (int kt = 0; kt < KT; kt++) {
        if (kt + 1 < KT) {
            issue(kt + 1, (kt + 1) & 1);
            asm volatile("cp.async.wait_group 1;" ::: "memory");
        } else {
            asm volatile("cp.async.wait_group 0;" ::: "memory");
        }
        __syncthreads();

        const uint32_t bufo = (uint32_t)(kt & 1) * GBUF;
        #pragma unroll
        for (int h16 = 0; h16 < 2; h16++) {
            uint32_t ah[4][4], al[4][4];
            #pragma unroll
            for (int mi = 0; mi < 4; mi++) {
                int row = wm * 64 + mi * 16 + grp;
                uint32_t base = sb + bufo + row * 80 + h16 * 32 + tig * 4;
                ah[mi][0] = lds32(base);
                ah[mi][1] = lds32(base + 8 * 80);
                ah[mi][2] = lds32(base + 16);
                ah[mi][3] = lds32(base + 8 * 80 + 16);
                al[mi][0] = lds32(base + GT_BYTES);
                al[mi][1] = lds32(base + GT_BYTES + 8 * 80);
                al[mi][2] = lds32(base + GT_BYTES + 16);
                al[mi][3] = lds32(base + GT_BYTES + 8 * 80 + 16);
            }
            uint32_t bh[4][2], bl[4][2];
            #pragma unroll
            for (int ni = 0; ni < 4; ni++) {
                int row = wn * 32 + ni * 8 + grp;
                uint32_t base = sb + bufo + 2 * GT_BYTES + row * 80 + h16 * 32 + tig * 4;
                bh[ni][0] = lds32(base);
                bh[ni][1] = lds32(base + 16);
                bl[ni][0] = lds32(base + GT_BYTES);
                bl[ni][1] = lds32(base + GT_BYTES + 16);
            }
            #pragma unroll
            for (int mi = 0; mi < 4; mi++)
                #pragma unroll
                for (int ni = 0; ni < 4; ni++) {
                    float* a = acc[mi][ni];
                    mma16816h(a[0], a[1], a[2], a[3],
                              ah[mi][0], ah[mi][1], ah[mi][2], ah[mi][3],
                              bh[ni][0], bh[ni][1]);
                    mma16816h(a[0], a[1], a[2], a[3],
                              ah[mi][0], ah[mi][1], ah[mi][2], ah[mi][3],
                              bl[ni][0], bl[ni][1]);
                    mma16816h(a[0], a[1], a[2], a[3],
                              al[mi][0], al[mi][1], al[mi][2], al[mi][3],
                              bh[ni][0], bh[ni][1]);
                }
        }
        __syncthreads();
    }

    #pragma unroll
    for (int ni = 0; ni < 4; ni++) {
        int gc = n0 + wn * 32 + ni * 8 + tig * 2;
        float bs0 = 0.f, bs1 = 0.f;
        if (bias1) { bs0 += bias1[gc]; bs1 += bias1[gc + 1]; }
        if (bias2) { bs0 += bias2[gc]; bs1 += bias2[gc + 1]; }
        #pragma unroll
        for (int mi = 0; mi < 4; mi++) {
            int gr = m0 + wm * 64 + mi * 16 + grp;
            float* a = acc[mi][ni];
            *(float2*)&C[(size_t)gr * N + gc] = make_float2(a[0] + bs0, a[1] + bs1);
            *(float2*)&C[(size_t)(gr + 8) * N + gc] = make_float2(a[2] + bs0, a[3] + bs1);
        }
    }
}

// ---------------- row softmax over 512 cols ---------------------------------
__global__ __launch_bounds__(256)
void softmax512(const float* __restrict__ logits, float* __restrict__ out)
{
    const int row = blockIdx.x;
    const int tid = threadIdx.x;
    const float* in = logits + (size_t)row * OO;
    float a = in[tid], b = in[tid + 256];

    float m = fmaxf(a, b);
    #pragma unroll
    for (int o = 16; o > 0; o >>= 1)
        m = fmaxf(m, __shfl_xor_sync(0xffffffffu, m, o));
    __shared__ float redm[8];
    __shared__ float reds[8];
    if ((tid & 31) == 0) redm[tid >> 5] = m;
    __syncthreads();
    float mm = redm[0];
    #pragma unroll
    for (int i = 1; i < 8; i++) mm = fmaxf(mm, redm[i]);

    float e0 = expf(a - mm), e1 = expf(b - mm);
    float s = e0 + e1;
    #pragma unroll
    for (int o = 16; o > 0; o >>= 1)
        s += __shfl_xor_sync(0xffffffffu, s, o);
    if ((tid & 31) == 0) reds[tid >> 5] = s;
    __syncthreads();
    float ss = 0.f;
    #pragma unroll
    for (int i = 0; i < 8; i++) ss += reds[i];
    float inv = 1.0f / ss;

    float* op = out + (size_t)row * OO;
    op[tid]       = e0 * inv;
    op[tid + 256] = e1 * inv;
}

// ---------------- launch -----------------------------------------------------
extern "C" void kernel_launch(void* const* d_in, const int* in_sizes, int n_in,
                              void* d_out, int out_size)
{
    const float* x     = (const float*)d_in[0];
    const float* h0    = (const float*)d_in[1];
    const float* W_ih  = (const float*)d_in[2];
    const float* W_hh  = (const float*)d_in[3];
    const float* b_ih  = (const float*)d_in[4];
    const float* b_hh  = (const float*)d_in[5];
    const float* W_out = (const float*)d_in[6];
    const float* b_out = (const float*)d_in[7];
    float* out = (float*)d_out;

    float *pre, *logits, *zfb;
    cudaGetSymbolAddress((void**)&pre,    g_pre);
    cudaGetSymbolAddress((void**)&logits, g_logits);
    cudaGetSymbolAddress((void**)&zfb,    g_zfallback);
    __half *xh, *xl, *wihh, *wihl, *wouth, *woutl, *zh16, *zl16;
    cudaGetSymbolAddress((void**)&xh, g_xh);
    cudaGetSymbolAddress((void**)&xl, g_xl);
    cudaGetSymbolAddress((void**)&wihh, g_wihh);
    cudaGetSymbolAddress((void**)&wihl, g_wihl);
    cudaGetSymbolAddress((void**)&wouth, g_wouth);
    cudaGetSymbolAddress((void**)&woutl, g_woutl);
    cudaGetSymbolAddress((void**)&zh16, g_zh16);
    cudaGetSymbolAddress((void**)&zl16, g_zl16);

    cudaFuncSetAttribute(hgemm, cudaFuncAttributeMaxDynamicSharedMemorySize, GSMEM);
    cudaFuncSetAttribute(rnn_persistent, cudaFuncAttributeMaxDynamicSharedMemorySize, RNN_SMEM);

    float* z = (out_size >= (int)((size_t)MM * (OO + HH)))
                 ? out + (size_t)MM * OO : zfb;

    // 0) fused prep: fp16-pair splits of x/W_ih/W_out + h0 convert
    prep_all<<<592, 256>>>(x, W_ih, W_out, h0);

    // 1) pre = x @ W_ih^T + b_ih + b_hh   (fp16-pair 3-term)
    dim3 g1(MM / 128, HH / 128);
    hgemm<<<g1, 256, GSMEM>>>(MM, HH, II, xh, xl, wihh, wihl, b_ih, b_hh, pre);

    // 2) recurrence (persistent, fp16 state, publishes zh16+zl16)
    rnn_persistent<<<RNN_BLOCKS, 256, RNN_SMEM>>>(pre, W_hh, z);

    // 3) logits = z @ W_out^T + b_out   (fp16-pair 3-term, consumes zh/zl)
    dim3 g3(MM / 128, OO / 128);
    hgemm<<<g3, 256, GSMEM>>>(MM, OO, HH, zh16, zl16, wouth, woutl, b_out, nullptr, logits);

    // 4) softmax rows -> out
    softmax512<<<MM, 256>>>(logits, out);
}